// round 1
// baseline (speedup 1.0000x reference)
#include <cuda_runtime.h>
#include <cuda_bf16.h>
#include <math.h>

// Problem constants
#define BATCH 4
#define H 1024
#define L 8192
#define KD 64
#define NS 4
#define TAPS 512   // KD * 2^(NS-1)

// Scratch (device globals: allocation-free rule)
__device__ float g_filt[H * TAPS];                         // 2 MB
__device__ float g_v[(size_t)BATCH * H * L];               // 128 MB (gelu'd conv output)

// ---------------------------------------------------------------------------
// Kernel 1: build the multi-resolution filter, L2-normalized per head.
// grid = H blocks, 512 threads (one per tap).
// ---------------------------------------------------------------------------
__global__ void build_filter_kernel(const float* __restrict__ k0,
                                    const float* __restrict__ k1,
                                    const float* __restrict__ k2,
                                    const float* __restrict__ k3) {
    int h = blockIdx.x;
    int t = threadIdx.x;  // 0..511

    const float* ks[NS] = {k0, k1, k2, k3};

    float acc = 0.0f;
#pragma unroll
    for (int i = 0; i < NS; ++i) {
        int len = KD << i;           // 64,128,256,512
        if (t < len) {
            float scale = (float)(1 << i);
            float coord = ((float)t + 0.5f) / scale - 0.5f;
            coord = fminf(fmaxf(coord, 0.0f), (float)(KD - 1));
            int lo = (int)floorf(coord);
            int hi = min(lo + 1, KD - 1);
            float w = coord - (float)lo;
            const float* kp = ks[i] + h * KD;   // C=1
            float v = kp[lo] * (1.0f - w) + kp[hi] * w;
            acc += v * (float)(1 << (NS - 1 - i));   // weights 8,4,2,1
        }
    }

    __shared__ float red[TAPS];
    red[t] = acc * acc;
    __syncthreads();
#pragma unroll
    for (int s = TAPS / 2; s > 0; s >>= 1) {
        if (t < s) red[t] += red[t + s];
        __syncthreads();
    }
    float inv_norm = rsqrtf(red[0]);
    g_filt[h * TAPS + t] = acc * inv_norm;
}

// ---------------------------------------------------------------------------
// Kernel 2: causal 512-tap FIR + D*u + exact GeLU -> g_v
// Sliding register window: each thread produces 8 consecutive outputs;
// per tap: 1 broadcast LDS (filter), 1 LDS (u), 8 FFMA.
// grid = (L/1024, B*H), block = 128 threads.
// ---------------------------------------------------------------------------
#define CONV_TILE 1024
#define CONV_THREADS 128
#define R 8

__global__ __launch_bounds__(CONV_THREADS)
void conv_gelu_kernel(const float* __restrict__ u, const float* __restrict__ D) {
    int bh = blockIdx.y;          // 0..B*H-1
    int h  = bh & (H - 1);
    int l0 = blockIdx.x * CONV_TILE;

    const float* up = u + (size_t)bh * L;
    float*       vp = g_v + (size_t)bh * L;

    __shared__ float k_s[TAPS];
    __shared__ float u_s[CONV_TILE + TAPS + 32];   // u_s[j] = u[l0 - 512 + j]

    int tid = threadIdx.x;
    for (int i = tid; i < TAPS; i += CONV_THREADS)
        k_s[i] = g_filt[h * TAPS + i];
    for (int i = tid; i < CONV_TILE + TAPS + 32; i += CONV_THREADS) {
        int gl = l0 - TAPS + i;
        u_s[i] = (gl >= 0 && gl < L) ? up[gl] : 0.0f;
    }
    __syncthreads();

    int p0 = tid * R;             // first output offset in tile

    float w[R], acc[R];
#pragma unroll
    for (int j = 0; j < R; ++j) {
        w[j]   = u_s[p0 + 1 + j]; // window for t = 511: u_s[p0 + j - 511 + 512]
        acc[j] = 0.0f;
    }

#pragma unroll 8
    for (int t = TAPS - 1; t >= 0; --t) {
        float kv = k_s[t];
#pragma unroll
        for (int j = 0; j < R; ++j)
            acc[j] = fmaf(kv, w[j], acc[j]);
        // slide window by one (register rotate after unroll)
#pragma unroll
        for (int j = 0; j < R - 1; ++j) w[j] = w[j + 1];
        w[R - 1] = u_s[p0 + (TAPS + R) - t];   // next iter (t-1), j=R-1
    }

    float d = D[h];   // C=1
#pragma unroll
    for (int j = 0; j < R; ++j) {
        float x = acc[j] + d * u_s[p0 + j + TAPS];
        float g = 0.5f * x * (1.0f + erff(x * 0.70710678118654752f));
        vp[l0 + p0 + j] = g;
    }
}

// ---------------------------------------------------------------------------
// Kernel 3: out[b,o,l] = sum_f W[o,f] * g_v[b,f,l] + bias[o]
// Classic 128x128x16 register-blocked SGEMM, 256 threads, 8x8 microtile.
// grid = (L/128, 1024/128, B)
// ---------------------------------------------------------------------------
#define BM 128
#define BN 128
#define BK 16
#define ASTR 132   // padded row stride for As (conflict-free transposed stores)

__global__ __launch_bounds__(256)
void gemm_bias_kernel(const float* __restrict__ Wm,
                      const float* __restrict__ bias,
                      float* __restrict__ out) {
    __shared__ float As[BK * ASTR];   // As[k][m] = W[m0+m][k0+k]
    __shared__ float Bs[BK * BN];     // Bs[k][n] = v[k0+k][n0+n]

    int bz = blockIdx.z;
    int m0 = blockIdx.y * BM;
    int n0 = blockIdx.x * BN;

    const float* v = g_v + (size_t)bz * H * L;

    int tid = threadIdx.x;     // 0..255
    int tx = tid & 15;         // n-subtile
    int ty = tid >> 4;         // m-subtile

    float acc[8][8];
#pragma unroll
    for (int i = 0; i < 8; ++i)
#pragma unroll
        for (int j = 0; j < 8; ++j) acc[i][j] = 0.0f;

    for (int k0 = 0; k0 < H; k0 += BK) {
        // --- load tiles (2 x float4 per thread each for A and B) ---
#pragma unroll
        for (int r = 0; r < 2; ++r) {
            int idx = tid + r * 256;
            // A: 128 rows x 16 cols -> 512 float4
            int arow = idx >> 2;
            int akq  = (idx & 3) * 4;
            float4 a4 = *(const float4*)(Wm + (size_t)(m0 + arow) * H + k0 + akq);
            As[(akq + 0) * ASTR + arow] = a4.x;
            As[(akq + 1) * ASTR + arow] = a4.y;
            As[(akq + 2) * ASTR + arow] = a4.z;
            As[(akq + 3) * ASTR + arow] = a4.w;
            // B: 16 rows x 128 cols -> 512 float4
            int brow = idx >> 5;
            int bq   = (idx & 31) * 4;
            float4 b4 = *(const float4*)(v + (size_t)(k0 + brow) * L + n0 + bq);
            *(float4*)(Bs + brow * BN + bq) = b4;
        }
        __syncthreads();

        // --- compute ---
#pragma unroll
        for (int k = 0; k < BK; ++k) {
            float4 a0 = *(const float4*)(As + k * ASTR + ty * 8);
            float4 a1 = *(const float4*)(As + k * ASTR + ty * 8 + 4);
            float4 b0 = *(const float4*)(Bs + k * BN + tx * 8);
            float4 b1 = *(const float4*)(Bs + k * BN + tx * 8 + 4);
            float a[8] = {a0.x, a0.y, a0.z, a0.w, a1.x, a1.y, a1.z, a1.w};
            float bb[8] = {b0.x, b0.y, b0.z, b0.w, b1.x, b1.y, b1.z, b1.w};
#pragma unroll
            for (int i = 0; i < 8; ++i)
#pragma unroll
                for (int j = 0; j < 8; ++j)
                    acc[i][j] = fmaf(a[i], bb[j], acc[i][j]);
        }
        __syncthreads();
    }

    // --- epilogue: + bias, vector stores ---
#pragma unroll
    for (int i = 0; i < 8; ++i) {
        int m = m0 + ty * 8 + i;
        float bv = bias[m];
        float* op = out + ((size_t)bz * H + m) * L + n0 + tx * 8;
        float4 o0 = make_float4(acc[i][0] + bv, acc[i][1] + bv,
                                acc[i][2] + bv, acc[i][3] + bv);
        float4 o1 = make_float4(acc[i][4] + bv, acc[i][5] + bv,
                                acc[i][6] + bv, acc[i][7] + bv);
        *(float4*)(op)     = o0;
        *(float4*)(op + 4) = o1;
    }
}

// ---------------------------------------------------------------------------
// Launch
// ---------------------------------------------------------------------------
extern "C" void kernel_launch(void* const* d_in, const int* in_sizes, int n_in,
                              void* d_out, int out_size) {
    const float* u  = (const float*)d_in[0];
    const float* k0 = (const float*)d_in[1];
    const float* k1 = (const float*)d_in[2];
    const float* k2 = (const float*)d_in[3];
    const float* k3 = (const float*)d_in[4];
    const float* D  = (const float*)d_in[5];
    const float* Wm = (const float*)d_in[6];
    const float* b  = (const float*)d_in[7];
    float* out = (float*)d_out;

    build_filter_kernel<<<H, TAPS>>>(k0, k1, k2, k3);

    dim3 cgrid(L / CONV_TILE, BATCH * H);
    conv_gelu_kernel<<<cgrid, CONV_THREADS>>>(u, D);

    dim3 ggrid(L / BN, H / BM, BATCH);
    gemm_bias_kernel<<<ggrid, 256>>>(Wm, b, out);
}

// round 4
// speedup vs baseline: 1.7002x; 1.7002x over previous
#include <cuda_runtime.h>
#include <cuda_bf16.h>
#include <cstdint>
#include <math.h>

// Problem constants
#define BATCH 4
#define H 1024
#define L 8192
#define KD 64
#define NS 4
#define TAPS 512

// Scratch
__device__ float g_filt[H * TAPS];                     // 2 MB
__device__ float g_v[(size_t)BATCH * H * L];           // 128 MB  v[b,f,l]

// ===========================================================================
// Helpers
// ===========================================================================
__device__ __forceinline__ uint32_t f2tf32(float x) {
    uint32_t r;
    asm("cvt.rna.tf32.f32 %0, %1;" : "=r"(r) : "f"(x));
    return r;
}

__device__ __forceinline__ void mma16n8k8(float d[4], const uint32_t a[4],
                                          const uint32_t b[2], const float c[4]) {
    asm volatile(
        "mma.sync.aligned.m16n8k8.row.col.f32.tf32.tf32.f32 "
        "{%0,%1,%2,%3}, {%4,%5,%6,%7}, {%8,%9}, {%10,%11,%12,%13};"
        : "=f"(d[0]), "=f"(d[1]), "=f"(d[2]), "=f"(d[3])
        : "r"(a[0]), "r"(a[1]), "r"(a[2]), "r"(a[3]),
          "r"(b[0]), "r"(b[1]),
          "f"(c[0]), "f"(c[1]), "f"(c[2]), "f"(c[3]));
}

// ===========================================================================
// Kernel 1: build the multi-resolution filter, L2-normalized per head.
// ===========================================================================
__global__ void build_filter_kernel(const float* __restrict__ k0,
                                    const float* __restrict__ k1,
                                    const float* __restrict__ k2,
                                    const float* __restrict__ k3) {
    int h = blockIdx.x;
    int t = threadIdx.x;

    const float* ks[NS] = {k0, k1, k2, k3};
    float acc = 0.0f;
#pragma unroll
    for (int i = 0; i < NS; ++i) {
        int len = KD << i;
        if (t < len) {
            float scale = (float)(1 << i);
            float coord = ((float)t + 0.5f) / scale - 0.5f;
            coord = fminf(fmaxf(coord, 0.0f), (float)(KD - 1));
            int lo = (int)floorf(coord);
            int hi = min(lo + 1, KD - 1);
            float w = coord - (float)lo;
            const float* kp = ks[i] + h * KD;
            float v = kp[lo] * (1.0f - w) + kp[hi] * w;
            acc += v * (float)(1 << (NS - 1 - i));
        }
    }

    __shared__ float red[TAPS];
    red[t] = acc * acc;
    __syncthreads();
#pragma unroll
    for (int s = TAPS / 2; s > 0; s >>= 1) {
        if (t < s) red[t] += red[t + s];
        __syncthreads();
    }
    float inv_norm = rsqrtf(red[0]);
    g_filt[h * TAPS + t] = acc * inv_norm;
}

// ===========================================================================
// Kernel 2: causal 512-tap FIR + D*u + exact GeLU -> g_v  (fp32)
// ===========================================================================
#define CONV_TILE 1024
#define CONV_THREADS 128
#define R 8

__global__ __launch_bounds__(CONV_THREADS)
void conv_gelu_kernel(const float* __restrict__ u, const float* __restrict__ D) {
    int bh = blockIdx.y;
    int h  = bh & (H - 1);
    int l0 = blockIdx.x * CONV_TILE;

    const float* up = u + (size_t)bh * L;
    float*       vp = g_v + (size_t)bh * L;

    __shared__ float k_s[TAPS];
    __shared__ float u_s[CONV_TILE + TAPS + 32];

    int tid = threadIdx.x;
    for (int i = tid; i < TAPS; i += CONV_THREADS)
        k_s[i] = g_filt[h * TAPS + i];
    for (int i = tid; i < CONV_TILE + TAPS + 32; i += CONV_THREADS) {
        int gl = l0 - TAPS + i;
        u_s[i] = (gl >= 0 && gl < L) ? up[gl] : 0.0f;
    }
    __syncthreads();

    int p0 = tid * R;
    float w[R], acc[R];
#pragma unroll
    for (int j = 0; j < R; ++j) {
        w[j]   = u_s[p0 + 1 + j];
        acc[j] = 0.0f;
    }

#pragma unroll 8
    for (int t = TAPS - 1; t >= 0; --t) {
        float kv = k_s[t];
#pragma unroll
        for (int j = 0; j < R; ++j)
            acc[j] = fmaf(kv, w[j], acc[j]);
#pragma unroll
        for (int j = 0; j < R - 1; ++j) w[j] = w[j + 1];
        w[R - 1] = u_s[p0 + (TAPS + R) - t];
    }

    float d = D[h];
#pragma unroll
    for (int j = 0; j < R; ++j) {
        float x = acc[j] + d * u_s[p0 + j + TAPS];
        float g = 0.5f * x * (1.0f + erff(x * 0.70710678118654752f));
        vp[l0 + p0 + j] = g;
    }
}

// ===========================================================================
// Kernel 3: tf32 mma.sync GEMM
//   out[b,o,l] = sum_f W[o,f] * v[b,f,l] + bias[o]
//   CTA tile 128(M=o) x 128(N=l) x BK=32; 8 warps (4M x 2N), warp 32x64.
// ===========================================================================
#define BM 128
#define BN 128
#define BK 32
#define AKS 36    // A_s row stride (words): [m][k], pad 32->36
#define BNS 136   // B_s row stride (words): [k][n], pad 128->136

__global__ __launch_bounds__(256, 2)
void gemm_mma_kernel(const float* __restrict__ Wm,
                     const float* __restrict__ bias,
                     float* __restrict__ out) {
    __shared__ uint32_t A_s[BM * AKS];   // A_s[m][k] = tf32(W[mb+m][k0+k])
    __shared__ uint32_t B_s[BK * BNS];   // B_s[k][n] = tf32(v[k0+k][nb+n])

    int bz = blockIdx.z;
    int nb = blockIdx.x * BN;       // l offset
    int mb = blockIdx.y * BM;       // o offset
    const float* v = g_v + (size_t)bz * H * L;

    int tid  = threadIdx.x;
    int lane = tid & 31;
    int wid  = tid >> 5;
    int wm = (wid & 3) * 32;        // warp m offset within tile
    int wn = (wid >> 2) * 64;       // warp n offset within tile
    int gid = lane >> 2;            // 0..7
    int tig = lane & 3;             // 0..3

    float acc[2][8][4];
#pragma unroll
    for (int i = 0; i < 2; ++i)
#pragma unroll
        for (int j = 0; j < 8; ++j)
#pragma unroll
            for (int q = 0; q < 4; ++q) acc[i][j][q] = 0.0f;

    for (int k0 = 0; k0 < H; k0 += BK) {
        // ---- load tiles: 4 float4 per thread for A and for B ----
#pragma unroll
        for (int r = 0; r < 4; ++r) {
            int idx = tid + r * 256;
            // A: 128 rows x 8 float4-slots
            int ar = idx >> 3, as = idx & 7;
            float4 a4 = *(const float4*)(Wm + (size_t)(mb + ar) * H + k0 + as * 4);
            uint4 at;
            at.x = f2tf32(a4.x); at.y = f2tf32(a4.y);
            at.z = f2tf32(a4.z); at.w = f2tf32(a4.w);
            *(uint4*)(A_s + ar * AKS + as * 4) = at;
            // B: 32 rows x 32 float4-slots
            int br = idx >> 5, bs = idx & 31;
            float4 b4 = *(const float4*)(v + (size_t)(k0 + br) * L + nb + bs * 4);
            uint4 bt;
            bt.x = f2tf32(b4.x); bt.y = f2tf32(b4.y);
            bt.z = f2tf32(b4.z); bt.w = f2tf32(b4.w);
            *(uint4*)(B_s + br * BNS + bs * 4) = bt;
        }
        __syncthreads();

        // ---- compute: 4 k-steps of 8 ----
#pragma unroll
        for (int kk = 0; kk < BK; kk += 8) {
            uint32_t af[2][4];
#pragma unroll
            for (int i = 0; i < 2; ++i) {
                int m0 = wm + i * 16;
                af[i][0] = A_s[(m0 + gid)     * AKS + kk + tig];
                af[i][1] = A_s[(m0 + gid + 8) * AKS + kk + tig];
                af[i][2] = A_s[(m0 + gid)     * AKS + kk + tig + 4];
                af[i][3] = A_s[(m0 + gid + 8) * AKS + kk + tig + 4];
            }
#pragma unroll
            for (int j = 0; j < 8; ++j) {
                uint32_t bf[2];
                bf[0] = B_s[(kk + tig)     * BNS + wn + j * 8 + gid];
                bf[1] = B_s[(kk + tig + 4) * BNS + wn + j * 8 + gid];
#pragma unroll
                for (int i = 0; i < 2; ++i)
                    mma16n8k8(acc[i][j], af[i], bf, acc[i][j]);
            }
        }
        __syncthreads();
    }

    // ---- epilogue: c0:(gid,2t) c1:(gid,2t+1) c2:(gid+8,2t) c3:(gid+8,2t+1)
#pragma unroll
    for (int i = 0; i < 2; ++i) {
        int r0 = mb + wm + i * 16 + gid;
        int r1 = r0 + 8;
        float bv0 = bias[r0];
        float bv1 = bias[r1];
        float* o0 = out + ((size_t)bz * H + r0) * L + nb + wn + tig * 2;
        float* o1 = out + ((size_t)bz * H + r1) * L + nb + wn + tig * 2;
#pragma unroll
        for (int j = 0; j < 8; ++j) {
            float2 lo = make_float2(acc[i][j][0] + bv0, acc[i][j][1] + bv0);
            float2 hi = make_float2(acc[i][j][2] + bv1, acc[i][j][3] + bv1);
            *(float2*)(o0 + j * 8) = lo;
            *(float2*)(o1 + j * 8) = hi;
        }
    }
}

// ===========================================================================
// Launch
// ===========================================================================
extern "C" void kernel_launch(void* const* d_in, const int* in_sizes, int n_in,
                              void* d_out, int out_size) {
    const float* u  = (const float*)d_in[0];
    const float* k0 = (const float*)d_in[1];
    const float* k1 = (const float*)d_in[2];
    const float* k2 = (const float*)d_in[3];
    const float* k3 = (const float*)d_in[4];
    const float* D  = (const float*)d_in[5];
    const float* Wm = (const float*)d_in[6];
    const float* b  = (const float*)d_in[7];
    float* out = (float*)d_out;

    build_filter_kernel<<<H, TAPS>>>(k0, k1, k2, k3);

    dim3 cgrid(L / CONV_TILE, BATCH * H);
    conv_gelu_kernel<<<cgrid, CONV_THREADS>>>(u, D);

    dim3 ggrid(L / BN, H / BM, BATCH);
    gemm_mma_kernel<<<ggrid, 256>>>(Wm, b, out);
}

// round 5
// speedup vs baseline: 3.3899x; 1.9938x over previous
#include <cuda_runtime.h>
#include <cuda_bf16.h>
#include <cstdint>
#include <math.h>

// Problem constants
#define BATCH 4
#define H 1024
#define L 8192
#define KD 64
#define NS 4
#define TAPS 512

// Scratch
__device__ float g_filt[H * TAPS];                     // 2 MB
__device__ float g_v[(size_t)BATCH * H * L];           // 128 MB  v[b,f,l]

// ===========================================================================
// Helpers
// ===========================================================================
__device__ __forceinline__ uint32_t f2tf32(float x) {
    uint32_t r;
    asm("cvt.rna.tf32.f32 %0, %1;" : "=r"(r) : "f"(x));
    return r;
}

__device__ __forceinline__ void mma16n8k8(float d[4], const uint32_t a[4],
                                          const uint32_t b[2], const float c[4]) {
    asm volatile(
        "mma.sync.aligned.m16n8k8.row.col.f32.tf32.tf32.f32 "
        "{%0,%1,%2,%3}, {%4,%5,%6,%7}, {%8,%9}, {%10,%11,%12,%13};"
        : "=f"(d[0]), "=f"(d[1]), "=f"(d[2]), "=f"(d[3])
        : "r"(a[0]), "r"(a[1]), "r"(a[2]), "r"(a[3]),
          "r"(b[0]), "r"(b[1]),
          "f"(c[0]), "f"(c[1]), "f"(c[2]), "f"(c[3]));
}

// ===========================================================================
// Kernel 1: build the multi-resolution filter, L2-normalized per head.
// ===========================================================================
__global__ void build_filter_kernel(const float* __restrict__ k0,
                                    const float* __restrict__ k1,
                                    const float* __restrict__ k2,
                                    const float* __restrict__ k3) {
    int h = blockIdx.x;
    int t = threadIdx.x;

    const float* ks[NS] = {k0, k1, k2, k3};
    float acc = 0.0f;
#pragma unroll
    for (int i = 0; i < NS; ++i) {
        int len = KD << i;
        if (t < len) {
            float scale = (float)(1 << i);
            float coord = ((float)t + 0.5f) / scale - 0.5f;
            coord = fminf(fmaxf(coord, 0.0f), (float)(KD - 1));
            int lo = (int)floorf(coord);
            int hi = min(lo + 1, KD - 1);
            float w = coord - (float)lo;
            const float* kp = ks[i] + h * KD;
            float v = kp[lo] * (1.0f - w) + kp[hi] * w;
            acc += v * (float)(1 << (NS - 1 - i));
        }
    }

    __shared__ float red[TAPS];
    red[t] = acc * acc;
    __syncthreads();
#pragma unroll
    for (int s = TAPS / 2; s > 0; s >>= 1) {
        if (t < s) red[t] += red[t + s];
        __syncthreads();
    }
    float inv_norm = rsqrtf(red[0]);
    g_filt[h * TAPS + t] = acc * inv_norm;
}

// ===========================================================================
// Kernel 2: Toeplitz-MMA conv: y = k (*) u  + D*u, GeLU -> g_v
//   Per CTA: one (b,h) row. GEMM view: M=128 blocks, N=64 positions, K=576.
//   A[r][c] = u[(r-d)*64+m], B[c][n] = k[n-m+64d], c = 64d+m.
//   Neither matrix materialized: affine index maps into smem.
//   4 warps, warp tile 64(M) x 32(N).
// ===========================================================================
#define UPAD_ROWS 136        // 8 guard rows (l<0) + 128 data rows
#define UPAD_STRIDE 68       // 64 + 4 pad words (bank-conflict-free stride)

__global__ __launch_bounds__(128)
void conv_mma_kernel(const float* __restrict__ u, const float* __restrict__ D) {
    __shared__ uint32_t u_s[UPAD_ROWS * UPAD_STRIDE];   // 9248 words
    __shared__ uint32_t k_s[640];                        // 64 zero | 512 filt | 64 zero

    int bh = blockIdx.x;
    int h  = bh & (H - 1);
    int tid  = threadIdx.x;
    int lane = tid & 31;
    int wid  = tid >> 5;
    int gid = lane >> 2;      // 0..7
    int tig = lane & 3;       // 0..3

    int wm0 = (wid & 1) * 64;   // warp block-offset (M)
    int wn0 = (wid >> 1) * 32;  // warp position-offset (N)

    const float* up = u + (size_t)bh * L;

    // ---- fill filter smem (with zero guards), tf32-rounded ----
    for (int i = tid; i < 640; i += 128) {
        int t = i - 64;
        float v = (t >= 0 && t < TAPS) ? g_filt[h * TAPS + t] : 0.0f;
        k_s[i] = f2tf32(v);
    }
    // ---- fill u smem: u_pad[(l+512)] at padded addr, tf32-rounded ----
    for (int j = tid; j < 512; j += 128)            // guard rows (l < 0)
        u_s[(j >> 6) * UPAD_STRIDE + (j & 63)] = 0u;
    for (int j = tid; j < L / 4; j += 128) {        // data, vectorized
        float4 x = ((const float4*)up)[j];
        int i = 512 + j * 4;
        uint32_t* p = u_s + (i >> 6) * UPAD_STRIDE + (i & 63);
        p[0] = f2tf32(x.x); p[1] = f2tf32(x.y);
        p[2] = f2tf32(x.z); p[3] = f2tf32(x.w);
    }
    __syncthreads();

    float acc[4][4][4];
#pragma unroll
    for (int s = 0; s < 4; ++s)
#pragma unroll
        for (int q = 0; q < 4; ++q)
#pragma unroll
            for (int e = 0; e < 4; ++e) acc[s][q][e] = 0.0f;

#pragma unroll 1
    for (int d = 0; d < 9; ++d) {
        int arow = (wm0 + gid + 8 - d) * UPAD_STRIDE + tig;
        int bb   = 64 + wn0 + gid - tig + 64 * d;
#pragma unroll
        for (int ms = 0; ms < 64; ms += 8) {
            uint32_t a[4][4];
#pragma unroll
            for (int s = 0; s < 4; ++s) {
                int base = arow + s * (16 * UPAD_STRIDE) + ms;
                a[s][0] = u_s[base];
                a[s][1] = u_s[base + 8 * UPAD_STRIDE];
                a[s][2] = u_s[base + 4];
                a[s][3] = u_s[base + 8 * UPAD_STRIDE + 4];
            }
            uint32_t bf[4][2];
#pragma unroll
            for (int q = 0; q < 4; ++q) {
                int kb = bb - ms + q * 8;
                bf[q][0] = k_s[kb];
                bf[q][1] = k_s[kb - 4];
            }
#pragma unroll
            for (int s = 0; s < 4; ++s)
#pragma unroll
                for (int q = 0; q < 4; ++q)
                    mma16n8k8(acc[s][q], a[s], bf[q], acc[s][q]);
        }
    }

    // ---- epilogue: + D*u, exact GeLU, store ----
    float dv = D[h];
    float* vp = g_v + (size_t)bh * L;
#pragma unroll
    for (int s = 0; s < 4; ++s) {
        int r0 = wm0 + s * 16 + gid;
#pragma unroll
        for (int q = 0; q < 4; ++q) {
            int n = wn0 + q * 8 + 2 * tig;
#pragma unroll
            for (int half = 0; half < 2; ++half) {
                int r = r0 + half * 8;
                float y0 = acc[s][q][half * 2 + 0];
                float y1 = acc[s][q][half * 2 + 1];
                float u0 = __uint_as_float(u_s[(r + 8) * UPAD_STRIDE + n]);
                float u1 = __uint_as_float(u_s[(r + 8) * UPAD_STRIDE + n + 1]);
                float x0 = y0 + dv * u0;
                float x1 = y1 + dv * u1;
                float g0 = 0.5f * x0 * (1.0f + erff(x0 * 0.70710678118654752f));
                float g1 = 0.5f * x1 * (1.0f + erff(x1 * 0.70710678118654752f));
                *(float2*)(vp + r * 64 + n) = make_float2(g0, g1);
            }
        }
    }
}

// ===========================================================================
// Kernel 3: tf32 mma.sync GEMM
//   out[b,o,l] = sum_f W[o,f] * v[b,f,l] + bias[o]
//   CTA tile 128(M=o) x 128(N=l) x BK=32; 8 warps (4M x 2N), warp 32x64.
// ===========================================================================
#define BM 128
#define BN 128
#define BK 32
#define AKS 36    // A_s row stride (words): [m][k], pad 32->36
#define BNS 136   // B_s row stride (words): [k][n], pad 128->136

__global__ __launch_bounds__(256, 2)
void gemm_mma_kernel(const float* __restrict__ Wm,
                     const float* __restrict__ bias,
                     float* __restrict__ out) {
    __shared__ uint32_t A_s[BM * AKS];   // A_s[m][k] = tf32(W[mb+m][k0+k])
    __shared__ uint32_t B_s[BK * BNS];   // B_s[k][n] = tf32(v[k0+k][nb+n])

    int bz = blockIdx.z;
    int nb = blockIdx.x * BN;       // l offset
    int mb = blockIdx.y * BM;       // o offset
    const float* v = g_v + (size_t)bz * H * L;

    int tid  = threadIdx.x;
    int lane = tid & 31;
    int wid  = tid >> 5;
    int wm = (wid & 3) * 32;        // warp m offset within tile
    int wn = (wid >> 2) * 64;       // warp n offset within tile
    int gid = lane >> 2;            // 0..7
    int tig = lane & 3;             // 0..3

    float acc[2][8][4];
#pragma unroll
    for (int i = 0; i < 2; ++i)
#pragma unroll
        for (int j = 0; j < 8; ++j)
#pragma unroll
            for (int q = 0; q < 4; ++q) acc[i][j][q] = 0.0f;

    for (int k0 = 0; k0 < H; k0 += BK) {
        // ---- load tiles: 4 float4 per thread for A and for B ----
#pragma unroll
        for (int r = 0; r < 4; ++r) {
            int idx = tid + r * 256;
            // A: 128 rows x 8 float4-slots
            int ar = idx >> 3, as = idx & 7;
            float4 a4 = *(const float4*)(Wm + (size_t)(mb + ar) * H + k0 + as * 4);
            uint4 at;
            at.x = f2tf32(a4.x); at.y = f2tf32(a4.y);
            at.z = f2tf32(a4.z); at.w = f2tf32(a4.w);
            *(uint4*)(A_s + ar * AKS + as * 4) = at;
            // B: 32 rows x 32 float4-slots
            int br = idx >> 5, bs = idx & 31;
            float4 b4 = *(const float4*)(v + (size_t)(k0 + br) * L + nb + bs * 4);
            uint4 bt;
            bt.x = f2tf32(b4.x); bt.y = f2tf32(b4.y);
            bt.z = f2tf32(b4.z); bt.w = f2tf32(b4.w);
            *(uint4*)(B_s + br * BNS + bs * 4) = bt;
        }
        __syncthreads();

        // ---- compute: 4 k-steps of 8 ----
#pragma unroll
        for (int kk = 0; kk < BK; kk += 8) {
            uint32_t af[2][4];
#pragma unroll
            for (int i = 0; i < 2; ++i) {
                int m0 = wm + i * 16;
                af[i][0] = A_s[(m0 + gid)     * AKS + kk + tig];
                af[i][1] = A_s[(m0 + gid + 8) * AKS + kk + tig];
                af[i][2] = A_s[(m0 + gid)     * AKS + kk + tig + 4];
                af[i][3] = A_s[(m0 + gid + 8) * AKS + kk + tig + 4];
            }
#pragma unroll
            for (int j = 0; j < 8; ++j) {
                uint32_t bf[2];
                bf[0] = B_s[(kk + tig)     * BNS + wn + j * 8 + gid];
                bf[1] = B_s[(kk + tig + 4) * BNS + wn + j * 8 + gid];
#pragma unroll
                for (int i = 0; i < 2; ++i)
                    mma16n8k8(acc[i][j], af[i], bf, acc[i][j]);
            }
        }
        __syncthreads();
    }

    // ---- epilogue: c0:(gid,2t) c1:(gid,2t+1) c2:(gid+8,2t) c3:(gid+8,2t+1)
#pragma unroll
    for (int i = 0; i < 2; ++i) {
        int r0 = mb + wm + i * 16 + gid;
        int r1 = r0 + 8;
        float bv0 = bias[r0];
        float bv1 = bias[r1];
        float* o0 = out + ((size_t)bz * H + r0) * L + nb + wn + tig * 2;
        float* o1 = out + ((size_t)bz * H + r1) * L + nb + wn + tig * 2;
#pragma unroll
        for (int j = 0; j < 8; ++j) {
            float2 lo = make_float2(acc[i][j][0] + bv0, acc[i][j][1] + bv0);
            float2 hi = make_float2(acc[i][j][2] + bv1, acc[i][j][3] + bv1);
            *(float2*)(o0 + j * 8) = lo;
            *(float2*)(o1 + j * 8) = hi;
        }
    }
}

// ===========================================================================
// Launch
// ===========================================================================
extern "C" void kernel_launch(void* const* d_in, const int* in_sizes, int n_in,
                              void* d_out, int out_size) {
    const float* u  = (const float*)d_in[0];
    const float* k0 = (const float*)d_in[1];
    const float* k1 = (const float*)d_in[2];
    const float* k2 = (const float*)d_in[3];
    const float* k3 = (const float*)d_in[4];
    const float* D  = (const float*)d_in[5];
    const float* Wm = (const float*)d_in[6];
    const float* b  = (const float*)d_in[7];
    float* out = (float*)d_out;

    build_filter_kernel<<<H, TAPS>>>(k0, k1, k2, k3);

    conv_mma_kernel<<<BATCH * H, 128>>>(u, D);

    dim3 ggrid(L / BN, H / BM, BATCH);
    gemm_mma_kernel<<<ggrid, 256>>>(Wm, b, out);
}